// round 1
// baseline (speedup 1.0000x reference)
#include <cuda_runtime.h>
#include <math.h>

// Problem dims (fixed by the dataset)
#define BATCH   32
#define STEPS   1024      // T
#define HD      1024      // D == H
#define BT      32768     // BATCH*STEPS rows
#define NCTA    128       // scan grid (all co-resident, 1 CTA/SM)
#define SCAN_THREADS 256

// ---------------- scratch (no allocations allowed) ----------------
__device__ float        g_xproj[(size_t)BT * HD];     // 128 MB input-proj result
__device__ float        g_hbuf[2][HD * BATCH];        // h double buffer, [o][b] layout
__device__ unsigned int g_bar[STEPS];                 // per-step grid barrier counters

// =================================================================
// GEMM (NT): C[M][N] = A[M][K] * W[N][K]^T + bias[N]   (K = N = HD)
// 128x128 tile, BK=16, 256 threads, 8x8 register tile
// =================================================================
#define GBM 128
#define GBN 128
#define GBK 16

__global__ __launch_bounds__(256, 2)
void gemm_nt_bias(const float* __restrict__ A, const float* __restrict__ W,
                  const float* __restrict__ bias, float* __restrict__ C) {
    __shared__ float As[GBK][GBM + 4];
    __shared__ float Ws[GBK][GBN + 4];

    const int tid = threadIdx.x;
    const int bm = blockIdx.y * GBM;
    const int bn = blockIdx.x * GBN;

    const int lr = tid >> 2;           // 0..63
    const int lc = (tid & 3) << 2;     // 0,4,8,12

    const int ty = tid >> 4;           // 0..15 -> m
    const int tx = tid & 15;           // 0..15 -> n

    float acc[8][8];
#pragma unroll
    for (int i = 0; i < 8; i++)
#pragma unroll
        for (int j = 0; j < 8; j++) acc[i][j] = 0.f;

    const float4* A4 = (const float4*)A;
    const float4* W4 = (const float4*)W;

    for (int kt = 0; kt < HD; kt += GBK) {
#pragma unroll
        for (int h = 0; h < 2; h++) {
            int row = bm + lr + h * 64;
            float4 v = A4[row * (HD / 4) + ((kt + lc) >> 2)];
            As[lc + 0][lr + h * 64] = v.x;
            As[lc + 1][lr + h * 64] = v.y;
            As[lc + 2][lr + h * 64] = v.z;
            As[lc + 3][lr + h * 64] = v.w;
        }
#pragma unroll
        for (int h = 0; h < 2; h++) {
            int row = bn + lr + h * 64;
            float4 v = W4[row * (HD / 4) + ((kt + lc) >> 2)];
            Ws[lc + 0][lr + h * 64] = v.x;
            Ws[lc + 1][lr + h * 64] = v.y;
            Ws[lc + 2][lr + h * 64] = v.z;
            Ws[lc + 3][lr + h * 64] = v.w;
        }
        __syncthreads();

#pragma unroll
        for (int k = 0; k < GBK; k++) {
            float4 a0 = *(const float4*)&As[k][ty * 8];
            float4 a1 = *(const float4*)&As[k][ty * 8 + 4];
            float4 w0 = *(const float4*)&Ws[k][tx * 8];
            float4 w1 = *(const float4*)&Ws[k][tx * 8 + 4];
            float a[8] = {a0.x, a0.y, a0.z, a0.w, a1.x, a1.y, a1.z, a1.w};
            float w[8] = {w0.x, w0.y, w0.z, w0.w, w1.x, w1.y, w1.z, w1.w};
#pragma unroll
            for (int i = 0; i < 8; i++)
#pragma unroll
                for (int j = 0; j < 8; j++) acc[i][j] += a[i] * w[j];
        }
        __syncthreads();
    }

    // epilogue: + bias, vector stores
#pragma unroll
    for (int i = 0; i < 8; i++) {
        int row = bm + ty * 8 + i;
        float* cp = &C[row * HD + bn + tx * 8];
#pragma unroll
        for (int j = 0; j < 8; j += 4) {
            float4 o;
            o.x = acc[i][j + 0] + bias[bn + tx * 8 + j + 0];
            o.y = acc[i][j + 1] + bias[bn + tx * 8 + j + 1];
            o.z = acc[i][j + 2] + bias[bn + tx * 8 + j + 2];
            o.w = acc[i][j + 3] + bias[bn + tx * 8 + j + 3];
            *(float4*)(cp + j) = o;
        }
    }
}

// =================================================================
// Persistent recurrent scan: h_{t} = gelu(xproj[:,t,:] + h_{t-1} Wh^T)
// 128 CTAs x 256 threads. CTA owns 8 output columns.
// Compute: 4b x 4o register tiles, K split 16 ways (64 k per thread).
// h exchanged via g_hbuf (double buffered, [o][b] layout) + grid barrier.
// =================================================================
__device__ __forceinline__ float gelu_exact(float x) {
    return 0.5f * x * (1.0f + erff(x * 0.70710678118654752f));
}

extern __shared__ float s_mem[];
// layout (floats): sWh [0, 8192)  = [k][oj] (8 cols)
//                  sH  [8192, 40960) = [k][b] (32 b)
//                  sPart [40960, 45056) = [kc][tile][16]

__global__ void scan_kernel(const float* __restrict__ xproj,
                            const float* __restrict__ Wh,
                            float* __restrict__ hidden) {
    float* sWh   = s_mem;
    float* sH    = s_mem + 8192;
    float* sPart = s_mem + 8192 + 32768;

    const int tid = threadIdx.x;
    const int o_base = blockIdx.x * 8;

    // load Wh slice transposed: sWh[k*8 + oj] = Wh[o_base+oj][k]
    const float4* Wh4 = (const float4*)Wh;
    for (int idx = tid; idx < 2048; idx += SCAN_THREADS) {
        int oj = idx >> 8;
        int k4 = idx & 255;
        float4 w = Wh4[(o_base + oj) * 256 + k4];
        int k = k4 << 2;
        sWh[(k + 0) * 8 + oj] = w.x;
        sWh[(k + 1) * 8 + oj] = w.y;
        sWh[(k + 2) * 8 + oj] = w.z;
        sWh[(k + 3) * 8 + oj] = w.w;
    }
    // zero h0
    float4* sH4 = (float4*)sH;
    float4 z4 = make_float4(0.f, 0.f, 0.f, 0.f);
    for (int i = tid; i < 8192; i += SCAN_THREADS) sH4[i] = z4;

    // compute-phase mapping: thread = (kc, bq, oq)
    const int kc   = tid >> 4;           // 0..15  (k chunk of 64)
    const int tile = tid & 15;           // 0..15
    const int bq   = tile >> 1;          // 0..7   (b = bq*4 + bi)
    const int oq   = tile & 1;           // 0..1   (o = oq*4 + oi)

    // reduce-phase mapping: thread = (b, oj)
    const int rb    = tid >> 3;          // 0..31
    const int roj   = tid & 7;           // 0..7
    const int rtile = ((rb >> 2) << 1) | (roj >> 2);
    const int re    = ((rb & 3) << 2) | (roj & 3);

    const float* hp = sH + bq * 4;
    const float* wp = sWh + oq * 4;
    const int kb = kc * 64;

    for (int s = 0; s < STEPS; s++) {
        __syncthreads();   // sH (staged h_{s-1}) visible

        float4 a0 = z4, a1 = z4, a2 = z4, a3 = z4;   // acc[bi][oi]
#pragma unroll 8
        for (int j = 0; j < 64; j++) {
            int k = kb + j;
            float4 hv = *(const float4*)(hp + k * 32);
            float4 wv = *(const float4*)(wp + k * 8);
            a0.x += hv.x * wv.x; a0.y += hv.x * wv.y; a0.z += hv.x * wv.z; a0.w += hv.x * wv.w;
            a1.x += hv.y * wv.x; a1.y += hv.y * wv.y; a1.z += hv.y * wv.z; a1.w += hv.y * wv.w;
            a2.x += hv.z * wv.x; a2.y += hv.z * wv.y; a2.z += hv.z * wv.z; a2.w += hv.z * wv.w;
            a3.x += hv.w * wv.x; a3.y += hv.w * wv.y; a3.z += hv.w * wv.z; a3.w += hv.w * wv.w;
        }
        float4* pp = (float4*)(sPart + kc * 256 + tile * 16);
        pp[0] = a0; pp[1] = a1; pp[2] = a2; pp[3] = a3;
        __syncthreads();   // partials visible; everyone done reading sH

        // reduce K-split partials, add x_t, GELU
        float v = 0.f;
#pragma unroll
        for (int q = 0; q < 16; q++)
            v += sPart[q * 256 + rtile * 16 + re];
        v += xproj[(rb * STEPS + s) * HD + o_base + roj];
        float hval = gelu_exact(v);

        hidden[(rb * STEPS + s) * HD + o_base + roj] = hval;
        g_hbuf[s & 1][(o_base + roj) * BATCH + rb] = hval;   // [o][b] layout
        __threadfence();
        __syncthreads();   // all STGs fenced before arrival

        if (tid == 0) {
            atomicAdd(&g_bar[s], 1u);
            while (((volatile unsigned int*)g_bar)[s] < NCTA) { }
        }
        __syncthreads();   // barrier done for whole CTA

        // stage h_s: [o][b] global layout == [k][b] smem layout, straight copy
        const float4* hb4 = (const float4*)g_hbuf[s & 1];
        for (int i = tid; i < 8192; i += SCAN_THREADS)
            sH4[i] = __ldcg(hb4 + i);    // bypass L1 (stale lines from prior stages)
    }
}

// =================================================================
extern "C" void kernel_launch(void* const* d_in, const int* in_sizes, int n_in,
                              void* d_out, int out_size) {
    const float* seq = (const float*)d_in[0];   // (B,T,D)
    const float* Wi  = (const float*)d_in[1];   // (H,D)
    const float* bi  = (const float*)d_in[2];   // (H,)
    const float* Wh  = (const float*)d_in[3];   // (H,H)
    const float* Wo  = (const float*)d_in[4];   // (H,H)
    const float* bo  = (const float*)d_in[5];   // (H,)

    float* out     = (float*)d_out;
    float* hidden  = out;                          // (B,T,H)
    float* outproj = out + (size_t)BT * HD;        // (B,T,H)

    void* xp_addr = 0;  cudaGetSymbolAddress(&xp_addr, g_xproj);
    void* bar_addr = 0; cudaGetSymbolAddress(&bar_addr, g_bar);

    // reset grid-barrier counters (graph-replay safe)
    cudaMemsetAsync(bar_addr, 0, STEPS * sizeof(unsigned int));

    dim3 gdim(HD / GBN, BT / GBM);   // (8, 256)

    // 1) input projection
    gemm_nt_bias<<<gdim, 256>>>(seq, Wi, bi, (float*)xp_addr);

    // 2) recurrent scan (persistent, grid-synchronized)
    const int smem_bytes = (8192 + 32768 + 4096) * (int)sizeof(float);  // 180224
    cudaFuncSetAttribute(scan_kernel, cudaFuncAttributeMaxDynamicSharedMemorySize, smem_bytes);
    scan_kernel<<<NCTA, SCAN_THREADS, smem_bytes>>>((const float*)xp_addr, Wh, hidden);

    // 3) output projection
    gemm_nt_bias<<<gdim, 256>>>(hidden, Wo, bo, outproj);
}

// round 4
// speedup vs baseline: 1.1778x; 1.1778x over previous
#include <cuda_runtime.h>
#include <cuda_bf16.h>
#include <math.h>
#include <stdint.h>

// Problem dims (fixed by the dataset)
#define BATCH   32
#define STEPS   1024      // T
#define HD      1024      // D == H
#define BT      32768     // BATCH*STEPS rows
#define NCTA    128       // scan grid (all co-resident, 1 CTA/SM)
#define SCAN_THREADS 256

// ---------------- scratch (no allocations allowed) ----------------
__device__ float         g_xproj[(size_t)BT * HD];     // 128 MB input-proj result
__device__ float         g_hbuf[2][HD * BATCH];        // h double buffer, [o][b] layout
__device__ unsigned int  g_bar[STEPS];                 // per-step grid barrier counters
__device__ __nv_bfloat16 g_Ahi[(size_t)BT * HD];       // 64 MB
__device__ __nv_bfloat16 g_Alo[(size_t)BT * HD];       // 64 MB
__device__ __nv_bfloat16 g_Bhi[HD * HD];               // 2 MB
__device__ __nv_bfloat16 g_Blo[HD * HD];               // 2 MB

// =================================================================
// helpers (plain sm_80-era PTX only: cp.async / ldmatrix / mma.sync)
// =================================================================
__device__ __forceinline__ uint32_t smem_u32(const void* p) {
    uint32_t a;
    asm("{ .reg .u64 t; cvta.to.shared.u64 t, %1; cvt.u32.u64 %0, t; }" : "=r"(a) : "l"(p));
    return a;
}
__device__ __forceinline__ void cp_async16(uint32_t dst, const void* src) {
    asm volatile("cp.async.cg.shared.global [%0], [%1], 16;" :: "r"(dst), "l"(src));
}
__device__ __forceinline__ void cp_commit() {
    asm volatile("cp.async.commit_group;");
}
__device__ __forceinline__ void cp_wait1() {
    asm volatile("cp.async.wait_group 1;");
}
__device__ __forceinline__ void ldsm_x4(uint32_t* r, uint32_t addr) {
    asm volatile("ldmatrix.sync.aligned.m8n8.x4.shared.b16 {%0,%1,%2,%3}, [%4];"
                 : "=r"(r[0]), "=r"(r[1]), "=r"(r[2]), "=r"(r[3]) : "r"(addr));
}
__device__ __forceinline__ void mma_bf16(float* c, const uint32_t* a, const uint32_t* b) {
    asm volatile(
        "mma.sync.aligned.m16n8k16.row.col.f32.bf16.bf16.f32 "
        "{%0,%1,%2,%3}, {%4,%5,%6,%7}, {%8,%9}, {%0,%1,%2,%3};"
        : "+f"(c[0]), "+f"(c[1]), "+f"(c[2]), "+f"(c[3])
        : "r"(a[0]), "r"(a[1]), "r"(a[2]), "r"(a[3]), "r"(b[0]), "r"(b[1]));
}

// =================================================================
// split fp32 -> bf16 hi + bf16 lo
// =================================================================
__global__ void split_bf16(const float* __restrict__ in,
                           __nv_bfloat16* __restrict__ hi,
                           __nv_bfloat16* __restrict__ lo, int n4) {
    int i = blockIdx.x * blockDim.x + threadIdx.x;
    if (i >= n4) return;
    float4 v = ((const float4*)in)[i];
    __nv_bfloat16 h0 = __float2bfloat16(v.x);
    __nv_bfloat16 h1 = __float2bfloat16(v.y);
    __nv_bfloat16 h2 = __float2bfloat16(v.z);
    __nv_bfloat16 h3 = __float2bfloat16(v.w);
    __nv_bfloat16 l0 = __float2bfloat16(v.x - __bfloat162float(h0));
    __nv_bfloat16 l1 = __float2bfloat16(v.y - __bfloat162float(h1));
    __nv_bfloat16 l2 = __float2bfloat16(v.z - __bfloat162float(h2));
    __nv_bfloat16 l3 = __float2bfloat16(v.w - __bfloat162float(h3));
    ((__nv_bfloat162*)hi)[2 * i + 0] = __halves2bfloat162(h0, h1);
    ((__nv_bfloat162*)hi)[2 * i + 1] = __halves2bfloat162(h2, h3);
    ((__nv_bfloat162*)lo)[2 * i + 0] = __halves2bfloat162(l0, l1);
    ((__nv_bfloat162*)lo)[2 * i + 1] = __halves2bfloat162(l2, l3);
}

// =================================================================
// HMMA split-bf16 GEMM (NT): C[M][N] = A[M][K] * W[N][K]^T + bias
//  CTA tile 128x128, BK=32, 256 threads (8 warps, 2x4 warp grid,
//  warp tile 64x32), 3-stage cp.async pipeline.
//  D accumulates Ahi*Bhi + Ahi*Blo + Alo*Bhi (fp32 regs).
// =================================================================
#define GSTAGES 3
#define TILE_B   10240            // 128 rows * 80 B (32 bf16 + 8 pad)
#define STAGE_B  (4 * TILE_B)     // Ahi, Alo, Bhi, Blo
#define ROWB     80

__global__ __launch_bounds__(256)
void mma_gemm(const __nv_bfloat16* __restrict__ Ahi, const __nv_bfloat16* __restrict__ Alo,
              const __nv_bfloat16* __restrict__ Bhi, const __nv_bfloat16* __restrict__ Blo,
              const float* __restrict__ bias, float* __restrict__ C) {
    extern __shared__ char dsm[];
    const uint32_t sb = smem_u32(dsm);

    const int tid = threadIdx.x;
    const int wid = tid >> 5;
    const int lane = tid & 31;
    const int bm = blockIdx.y * 128;
    const int bn = blockIdx.x * 128;
    const int wm = (wid >> 2) * 64;      // 0 or 64
    const int wn = (wid & 3) * 32;       // 0,32,64,96

    // ---- loader mapping: tile = tid>>6 (Ahi,Alo,Bhi,Blo), 64 thr/tile ----
    const int lt  = tid >> 6;            // 0..3
    const int lid = tid & 63;            // 0..63
    const __nv_bfloat16* lsrc = (lt == 0) ? Ahi : (lt == 1) ? Alo : (lt == 2) ? Bhi : Blo;
    const int lrowb = (lt < 2) ? bm : bn;

    float acc[4][4][4];
#pragma unroll
    for (int i = 0; i < 4; i++)
#pragma unroll
        for (int j = 0; j < 4; j++)
#pragma unroll
            for (int e = 0; e < 4; e++) acc[i][j][e] = 0.f;

    // prologue: load stages 0,1
#pragma unroll
    for (int ps = 0; ps < GSTAGES - 1; ps++) {
        uint32_t dstb = sb + ps * STAGE_B + lt * TILE_B;
#pragma unroll
        for (int i = 0; i < 8; i++) {
            int idx = i * 64 + lid;                  // 0..511
            int r = idx >> 2, c = idx & 3;
            cp_async16(dstb + r * ROWB + c * 16,
                       lsrc + (size_t)(lrowb + r) * HD + ps * 32 + c * 8);
        }
        cp_commit();
    }

    for (int kt = 0; kt < HD / 32; kt++) {
        cp_wait1();
        __syncthreads();

        // prefetch stage kt+2
        if (kt + GSTAGES - 1 < HD / 32) {
            uint32_t dstb = sb + ((kt + GSTAGES - 1) % GSTAGES) * STAGE_B + lt * TILE_B;
#pragma unroll
            for (int i = 0; i < 8; i++) {
                int idx = i * 64 + lid;
                int r = idx >> 2, c = idx & 3;
                cp_async16(dstb + r * ROWB + c * 16,
                           lsrc + (size_t)(lrowb + r) * HD + (kt + GSTAGES - 1) * 32 + c * 8);
            }
        }
        cp_commit();

        // ---- compute this stage: 2 ksteps of 16 ----
        uint32_t stg = sb + (kt % GSTAGES) * STAGE_B;
        uint32_t aBaseH = stg + 0 * TILE_B;
        uint32_t aBaseL = stg + 1 * TILE_B;
        uint32_t bBaseH = stg + 2 * TILE_B;
        uint32_t bBaseL = stg + 3 * TILE_B;

#pragma unroll
        for (int ks = 0; ks < 2; ks++) {
            uint32_t ah[4][4], al[4][4], bh[4][2], bl[4][2];
            // A frags: row = wm + mt*16 + (lane&15); +16B col for lanes>=16
            int arow = (lane & 15);
            int acol = (lane >> 4) * 16 + ks * 32;
#pragma unroll
            for (int mt = 0; mt < 4; mt++) {
                ldsm_x4(ah[mt], aBaseH + (wm + mt * 16 + arow) * ROWB + acol);
                ldsm_x4(al[mt], aBaseL + (wm + mt * 16 + arow) * ROWB + acol);
            }
            // B frags: x4 covers 16 n-rows (two n8 tiles)
            int brow = ((lane >> 4) << 3) + (lane & 7);
            int bcol = ((lane >> 3) & 1) * 16 + ks * 32;
#pragma unroll
            for (int p = 0; p < 2; p++) {
                uint32_t t[4];
                ldsm_x4(t, bBaseH + (wn + p * 16 + brow) * ROWB + bcol);
                bh[2 * p][0] = t[0]; bh[2 * p][1] = t[1];
                bh[2 * p + 1][0] = t[2]; bh[2 * p + 1][1] = t[3];
                ldsm_x4(t, bBaseL + (wn + p * 16 + brow) * ROWB + bcol);
                bl[2 * p][0] = t[0]; bl[2 * p][1] = t[1];
                bl[2 * p + 1][0] = t[2]; bl[2 * p + 1][1] = t[3];
            }
#pragma unroll
            for (int mt = 0; mt < 4; mt++)
#pragma unroll
                for (int nt = 0; nt < 4; nt++) {
                    mma_bf16(acc[mt][nt], ah[mt], bh[nt]);
                    mma_bf16(acc[mt][nt], ah[mt], bl[nt]);
                    mma_bf16(acc[mt][nt], al[mt], bh[nt]);
                }
        }
    }

    // ---- epilogue: acc -> C + bias ----
#pragma unroll
    for (int mt = 0; mt < 4; mt++) {
#pragma unroll
        for (int nt = 0; nt < 4; nt++) {
            int m0 = bm + wm + mt * 16 + (lane >> 2);
            int n0 = bn + wn + nt * 8 + (lane & 3) * 2;
            float b0 = bias[n0], b1 = bias[n0 + 1];
            float2 v0 = make_float2(acc[mt][nt][0] + b0, acc[mt][nt][1] + b1);
            float2 v1 = make_float2(acc[mt][nt][2] + b0, acc[mt][nt][3] + b1);
            *(float2*)&C[(size_t)m0 * HD + n0] = v0;
            *(float2*)&C[(size_t)(m0 + 8) * HD + n0] = v1;
        }
    }
}

// =================================================================
// Persistent recurrent scan (R1 + xproj prefetch + split barrier)
// =================================================================
__device__ __forceinline__ float gelu_exact(float x) {
    return 0.5f * x * (1.0f + erff(x * 0.70710678118654752f));
}

extern __shared__ float s_mem[];

__global__ void scan_kernel(const float* __restrict__ xproj,
                            const float* __restrict__ Wh,
                            float* __restrict__ hidden) {
    float* sWh   = s_mem;
    float* sH    = s_mem + 8192;
    float* sPart = s_mem + 8192 + 32768;

    const int tid = threadIdx.x;
    const int o_base = blockIdx.x * 8;

    const float4* Wh4 = (const float4*)Wh;
    for (int idx = tid; idx < 2048; idx += SCAN_THREADS) {
        int oj = idx >> 8;
        int k4 = idx & 255;
        float4 w = Wh4[(o_base + oj) * 256 + k4];
        int k = k4 << 2;
        sWh[(k + 0) * 8 + oj] = w.x;
        sWh[(k + 1) * 8 + oj] = w.y;
        sWh[(k + 2) * 8 + oj] = w.z;
        sWh[(k + 3) * 8 + oj] = w.w;
    }
    float4* sH4 = (float4*)sH;
    float4 z4 = make_float4(0.f, 0.f, 0.f, 0.f);
    for (int i = tid; i < 8192; i += SCAN_THREADS) sH4[i] = z4;

    const int kc   = tid >> 4;
    const int tile = tid & 15;
    const int bq   = tile >> 1;
    const int oq   = tile & 1;

    const int rb    = tid >> 3;
    const int roj   = tid & 7;
    const int rtile = ((rb >> 2) << 1) | (roj >> 2);
    const int re    = ((rb & 3) << 2) | (roj & 3);

    const float* hp = sH + bq * 4;
    const float* wp = sWh + oq * 4;
    const int kb = kc * 64;

    // prefetch xproj for step 0
    float xv = xproj[(rb * STEPS + 0) * HD + o_base + roj];

    for (int s = 0; s < STEPS; s++) {
        __syncthreads();   // sH (staged h_{s-1}) visible

        float4 a0 = z4, a1 = z4, a2 = z4, a3 = z4;
#pragma unroll 8
        for (int j = 0; j < 64; j++) {
            int k = kb + j;
            float4 hv = *(const float4*)(hp + k * 32);
            float4 wv = *(const float4*)(wp + k * 8);
            a0.x += hv.x * wv.x; a0.y += hv.x * wv.y; a0.z += hv.x * wv.z; a0.w += hv.x * wv.w;
            a1.x += hv.y * wv.x; a1.y += hv.y * wv.y; a1.z += hv.y * wv.z; a1.w += hv.y * wv.w;
            a2.x += hv.z * wv.x; a2.y += hv.z * wv.y; a2.z += hv.z * wv.z; a2.w += hv.z * wv.w;
            a3.x += hv.w * wv.x; a3.y += hv.w * wv.y; a3.z += hv.w * wv.z; a3.w += hv.w * wv.w;
        }
        float4* pp = (float4*)(sPart + kc * 256 + tile * 16);
        pp[0] = a0; pp[1] = a1; pp[2] = a2; pp[3] = a3;
        __syncthreads();

        float v = 0.f;
#pragma unroll
        for (int q = 0; q < 16; q++)
            v += sPart[q * 256 + rtile * 16 + re];
        v += xv;
        float hval = gelu_exact(v);

        hidden[(rb * STEPS + s) * HD + o_base + roj] = hval;
        g_hbuf[s & 1][(o_base + roj) * BATCH + rb] = hval;
        __threadfence();
        __syncthreads();   // all stores fenced before arrival

        if (tid == 0) atomicAdd(&g_bar[s], 1u);   // arrive early

        // overlap: prefetch next step's xproj while the barrier fills
        float xnext = 0.f;
        if (s + 1 < STEPS)
            xnext = xproj[(rb * STEPS + s + 1) * HD + o_base + roj];

        if (tid == 0) {
            while (((volatile unsigned int*)g_bar)[s] < NCTA) { }
        }
        __syncthreads();

        const float4* hb4 = (const float4*)g_hbuf[s & 1];
        for (int i = tid; i < 8192; i += SCAN_THREADS)
            sH4[i] = __ldcg(hb4 + i);

        xv = xnext;
    }
}

// =================================================================
extern "C" void kernel_launch(void* const* d_in, const int* in_sizes, int n_in,
                              void* d_out, int out_size) {
    const float* seq = (const float*)d_in[0];   // (B,T,D)
    const float* Wi  = (const float*)d_in[1];   // (H,D)
    const float* bi  = (const float*)d_in[2];   // (H,)
    const float* Wh  = (const float*)d_in[3];   // (H,H)
    const float* Wo  = (const float*)d_in[4];   // (H,H)
    const float* bo  = (const float*)d_in[5];   // (H,)

    float* out     = (float*)d_out;
    float* hidden  = out;                          // (B,T,H)
    float* outproj = out + (size_t)BT * HD;        // (B,T,H)

    void *xp_addr = 0, *bar_addr = 0, *ahi = 0, *alo = 0, *bhi = 0, *blo = 0;
    cudaGetSymbolAddress(&xp_addr, g_xproj);
    cudaGetSymbolAddress(&bar_addr, g_bar);
    cudaGetSymbolAddress(&ahi, g_Ahi);
    cudaGetSymbolAddress(&alo, g_Alo);
    cudaGetSymbolAddress(&bhi, g_Bhi);
    cudaGetSymbolAddress(&blo, g_Blo);

    cudaMemsetAsync(bar_addr, 0, STEPS * sizeof(unsigned int));

    const int nA4 = BT * HD / 4;       // 8388608
    const int nW4 = HD * HD / 4;       // 262144
    const int gemm_smem = GSTAGES * STAGE_B;   // 122880
    cudaFuncSetAttribute(mma_gemm, cudaFuncAttributeMaxDynamicSharedMemorySize, gemm_smem);
    dim3 ggrid(HD / 128, BT / 128);    // (8, 256)

    // 1) input projection: xproj = seq @ Wi^T + bi  (split-bf16 HMMA)
    split_bf16<<<nA4 / 256, 256>>>(seq, (__nv_bfloat16*)ahi, (__nv_bfloat16*)alo, nA4);
    split_bf16<<<nW4 / 256, 256>>>(Wi, (__nv_bfloat16*)bhi, (__nv_bfloat16*)blo, nW4);
    mma_gemm<<<ggrid, 256, gemm_smem>>>((const __nv_bfloat16*)ahi, (const __nv_bfloat16*)alo,
                                        (const __nv_bfloat16*)bhi, (const __nv_bfloat16*)blo,
                                        bi, (float*)xp_addr);

    // 2) recurrent scan (persistent, grid-synchronized, fp32)
    const int scan_smem = (8192 + 32768 + 4096) * (int)sizeof(float);  // 180224
    cudaFuncSetAttribute(scan_kernel, cudaFuncAttributeMaxDynamicSharedMemorySize, scan_smem);
    scan_kernel<<<NCTA, SCAN_THREADS, scan_smem>>>((const float*)xp_addr, Wh, hidden);

    // 3) output projection: out = hidden @ Wo^T + bo  (split-bf16 HMMA)
    split_bf16<<<nA4 / 256, 256>>>(hidden, (__nv_bfloat16*)ahi, (__nv_bfloat16*)alo, nA4);
    split_bf16<<<nW4 / 256, 256>>>(Wo, (__nv_bfloat16*)bhi, (__nv_bfloat16*)blo, nW4);
    mma_gemm<<<ggrid, 256, gemm_smem>>>((const __nv_bfloat16*)ahi, (const __nv_bfloat16*)alo,
                                        (const __nv_bfloat16*)bhi, (const __nv_bfloat16*)blo,
                                        bo, outproj);
}